// round 14
// baseline (speedup 1.0000x reference)
#include <cuda_runtime.h>
#include <cuda_fp16.h>
#include <cstdint>

#define BB 32
#define CC 512
#define LL 1024
#define LPAD (LL + 2)

// ---------------------------------------------------------------------------
// Scratch (static device globals -- allocation-free per harness rules)
// ---------------------------------------------------------------------------
__device__ float g_act[BB*CC*LL];                   // conv output [B,C,L]
__device__ unsigned int g_xq[BB*LL*(CC/4)];         // packed int8 activations [B,L,C/4]
__device__ float g_arecip[BB*LL];                   // per-token absmax/127
__device__ float g_mean[CC];
__device__ float g_rstd[CC];
__device__ float g_wrecip_d;
__device__ float g_wscale_d;
__device__ float g_wpart[64];
__device__ unsigned int g_wq[CC*(CC/4)];            // packed ternary weights [O,C/4]
__device__ float g_psumT[256][CC];                  // [b*8+ltile][c] partial sums
__device__ float g_psqT[256][CC];
__device__ unsigned int g_arrive;                   // persistent-grid barrier
__device__ unsigned int g_done;

// fp16 split operands for tensor-core conv
__device__ __half g_xhiT[BB*LPAD*CC];               // x transposed [b][l+1][i], hi
__device__ __half g_xloT[BB*LPAD*CC];               // lo
__device__ __half g_whi[3*CC*CC];                   // w [tap][c][i], hi only

__device__ __forceinline__ float gelu_f(float v){
    return 0.5f*v*(1.0f + erff(v*0.70710678118654752440f));
}

__device__ __forceinline__ uint32_t smem_to_u32(const void* smem_ptr) {
    uint32_t addr;
    asm("{ .reg .u64 tmp; cvta.to.shared.u64 tmp, %1; cvt.u32.u64 %0, tmp; }"
        : "=r"(addr) : "l"(smem_ptr));
    return addr;
}

#define CP_ASYNC16(dst_u32, src_ptr) \
    asm volatile("cp.async.cg.shared.global [%0], [%1], 16;" \
        :: "r"(dst_u32), "l"(src_ptr))
#define CP_COMMIT() asm volatile("cp.async.commit_group;" ::: "memory")
#define CP_WAIT1()  asm volatile("cp.async.wait_group 1;" ::: "memory")
#define CP_WAIT0()  asm volatile("cp.async.wait_group 0;" ::: "memory")

#define LDSM4(r0,r1,r2,r3,addr) \
    asm volatile("ldmatrix.sync.aligned.m8n8.x4.shared.b16 {%0,%1,%2,%3}, [%4];" \
        : "=r"(r0),"=r"(r1),"=r"(r2),"=r"(r3) : "r"(addr))

#define MMA16816(c, a, b0, b1) \
    asm volatile("mma.sync.aligned.m16n8k16.row.col.f32.f16.f16.f32 " \
        "{%0,%1,%2,%3}, {%4,%5,%6,%7}, {%8,%9}, {%0,%1,%2,%3};" \
        : "+f"((c)[0]),"+f"((c)[1]),"+f"((c)[2]),"+f"((c)[3]) \
        : "r"((a)[0]),"r"((a)[1]),"r"((a)[2]),"r"((a)[3]), "r"(b0),"r"(b1))

#define IMMA16832(c, a, b0, b1) \
    asm volatile("mma.sync.aligned.m16n8k32.row.col.s32.s8.s8.s32 " \
        "{%0,%1,%2,%3}, {%4,%5,%6,%7}, {%8,%9}, {%0,%1,%2,%3};" \
        : "+r"((c)[0]),"+r"((c)[1]),"+r"((c)[2]),"+r"((c)[3]) \
        : "r"((a)[0]),"r"((a)[1]),"r"((a)[2]),"r"((a)[3]), "r"(b0),"r"(b1))

// ---------------------------------------------------------------------------
// P1: transpose + fp16 split of x, half2 stores; halo rows fused in.
// ---------------------------------------------------------------------------
__global__ __launch_bounds__(256) void prep_x_kernel(const float* __restrict__ x){
    __shared__ float ts[32][33];
    const int b  = blockIdx.z;
    const int i0 = blockIdx.y*32;
    const int l0 = blockIdx.x*32;
    const int tx = threadIdx.x & 31, ty = threadIdx.x >> 5;

    if (blockIdx.x == 0 && threadIdx.x < 64){
        const int r = threadIdx.x >> 5;
        const int i = i0 + (threadIdx.x & 31);
        size_t o = ((size_t)b*LPAD + (r ? LPAD-1 : 0))*CC + i;
        g_xhiT[o] = __float2half(0.f);
        g_xloT[o] = __float2half(0.f);
    }

    #pragma unroll
    for (int ii = ty; ii < 32; ii += 8)
        ts[ii][tx] = x[((size_t)b*CC + i0 + ii)*LL + l0 + tx];
    __syncthreads();
    const int ip = threadIdx.x & 15;
    const int lr = threadIdx.x >> 4;
    #pragma unroll
    for (int pass = 0; pass < 2; pass++){
        const int ll = lr + pass*16;
        float v0 = ts[2*ip  ][ll];
        float v1 = ts[2*ip+1][ll];
        __half h0 = __float2half(v0);
        __half h1 = __float2half(v1);
        __half e0 = __float2half(v0 - __half2float(h0));
        __half e1 = __float2half(v1 - __half2float(h1));
        size_t o = ((size_t)b*LPAD + l0 + ll + 1)*CC + i0 + 2*ip;
        *(__half2*)&g_xhiT[o] = __halves2half2(h0, h1);
        *(__half2*)&g_xloT[o] = __halves2half2(e0, e1);
    }
}

// P2: conv_w [c][i][3] -> g_whi [tap][c][i] fp16, half2 writes
__global__ __launch_bounds__(256) void prep_w_kernel(const float* __restrict__ w){
    int idx = blockIdx.x*256 + threadIdx.x;      // 131072
    int c = idx >> 8, jp = idx & 255;
    int i0 = jp*2;
    const float* src = w + ((size_t)c*CC + i0)*3;
    #pragma unroll
    for (int k = 0; k < 3; k++){
        __half h0 = __float2half(src[k]);
        __half h1 = __float2half(src[3+k]);
        *(__half2*)&g_whi[((size_t)k*CC + c)*CC + i0] = __halves2half2(h0, h1);
    }
}

// ---------------------------------------------------------------------------
// K1: Persistent Conv1d fp16-split HMMA (grid = 296, 2 CTA/SM, tile loop),
//     fused BN partials AND fused final BN reduce via persistent-grid barrier.
// ---------------------------------------------------------------------------
#define WTILE_B 10240               // 128 rows * 80B
#define XTILE_B 10400               // 130 rows * 80B
#define STAGE_B (3*WTILE_B + 2*XTILE_B)   // 51520
#define CONV_SMEM (2*STAGE_B)             // 103040
#define CONV_GRID 296
#define N_TILES 1024

__global__ __launch_bounds__(256, 2) void conv_mma_kernel(const float* __restrict__ bias){
    extern __shared__ char smem[];
    __shared__ float psum[128][4];
    __shared__ float psq[128][4];
    __shared__ float ss[4][64], qq[4][64];
    const uint32_t sbase = smem_to_u32(smem);
    const int tid = threadIdx.x;
    const int lane = tid & 31, wid = tid >> 5;
    const int wc = wid & 1, wl = wid >> 1;

    for (int tile = blockIdx.x; tile < N_TILES; tile += CONV_GRID){
        const int b  = tile >> 5;
        const int c0 = ((tile >> 3) & 3) << 7;
        const int lt = tile & 7;
        const int l0 = lt << 7;

        float acc[4][4][4];
        #pragma unroll
        for (int i=0;i<4;i++)
            #pragma unroll
            for (int j=0;j<4;j++)
                #pragma unroll
                for (int q=0;q<4;q++) acc[i][j][q]=0.f;

        #define ISSUE(kc, stg) do { \
            const uint32_t st_ = sbase + (stg)*STAGE_B; \
            const int koff_ = (kc)*32; \
            for (int idx = tid; idx < 1536; idx += 256){ \
                const int tap_ = idx >> 9, r_ = (idx >> 2) & 127, ch_ = idx & 3; \
                CP_ASYNC16(st_ + tap_*WTILE_B + r_*80 + ch_*16, \
                           g_whi + ((size_t)(tap_*CC + c0 + r_))*CC + koff_ + ch_*8); \
            } \
            for (int idx = tid; idx < 1040; idx += 256){ \
                const int t_ = (idx >= 520) ? 1 : 0; \
                const int w_ = idx - t_*520; \
                const int r_ = w_ >> 2, ch_ = w_ & 3; \
                const __half* src_ = (t_ ? g_xloT : g_xhiT) \
                    + ((size_t)b*LPAD + l0 + r_)*CC + koff_ + ch_*8; \
                CP_ASYNC16(st_ + 3*WTILE_B + t_*XTILE_B + r_*80 + ch_*16, src_); \
            } \
        } while(0)

        ISSUE(0, 0);
        CP_COMMIT();
        ISSUE(1, 1);
        CP_COMMIT();

        for (int kc = 0; kc < 16; kc++){
            if (kc + 1 < 16) CP_WAIT1(); else CP_WAIT0();
            __syncthreads();

            const uint32_t st = sbase + (kc & 1)*STAGE_B;
            const uint32_t xb = st + 3*WTILE_B;
            #pragma unroll
            for (int kh = 0; kh < 2; kh++){
                const uint32_t colb = (uint32_t)(kh*32 + (lane >> 4)*16);
                #pragma unroll
                for (int tap = 0; tap < 3; tap++){
                    uint32_t a[4][4];
                    #pragma unroll
                    for (int mf = 0; mf < 4; mf++){
                        const uint32_t r = (uint32_t)(wc*64 + mf*16 + (lane & 15));
                        LDSM4(a[mf][0],a[mf][1],a[mf][2],a[mf][3],
                              st + tap*WTILE_B + r*80 + colb);
                    }
                    uint32_t bhi[4][2], blo[4][2];
                    #pragma unroll
                    for (int g = 0; g < 2; g++){
                        const uint32_t r = (uint32_t)(tap + wl*32 + g*16 + (lane & 15));
                        uint32_t t0,t1,t2,t3;
                        LDSM4(t0,t1,t2,t3, xb + r*80 + colb);
                        bhi[g*2][0]=t0; bhi[g*2+1][0]=t1; bhi[g*2][1]=t2; bhi[g*2+1][1]=t3;
                        LDSM4(t0,t1,t2,t3, xb + XTILE_B + r*80 + colb);
                        blo[g*2][0]=t0; blo[g*2+1][0]=t1; blo[g*2][1]=t2; blo[g*2+1][1]=t3;
                    }
                    #pragma unroll
                    for (int mf = 0; mf < 4; mf++){
                        #pragma unroll
                        for (int nf = 0; nf < 4; nf++){
                            MMA16816(acc[mf][nf], a[mf], bhi[nf][0], bhi[nf][1]);
                            MMA16816(acc[mf][nf], a[mf], blo[nf][0], blo[nf][1]);
                        }
                    }
                }
            }
            __syncthreads();
            if (kc + 2 < 16){
                ISSUE(kc+2, kc & 1);
                CP_COMMIT();
            }
        }
        #undef ISSUE

        // ---- epilogue: bias + store + BN partials ----
        const int lcol = l0 + wl*32 + (lane & 3)*2;
        #pragma unroll
        for (int mf = 0; mf < 4; mf++){
            const int rbase = c0 + wc*64 + mf*16 + (lane >> 2);
            #pragma unroll
            for (int half = 0; half < 2; half++){
                const int c = rbase + half*8;
                const float bv = bias[c];
                float* dst = &g_act[((size_t)b*CC + c)*LL + lcol];
                float s = 0.f, q = 0.f;
                #pragma unroll
                for (int nf = 0; nf < 4; nf++){
                    float2 v;
                    v.x = acc[mf][nf][half*2+0] + bv;
                    v.y = acc[mf][nf][half*2+1] + bv;
                    *(float2*)(dst + nf*8) = v;
                    s += v.x + v.y;
                    q += v.x*v.x + v.y*v.y;
                }
                s += __shfl_xor_sync(0xffffffffu, s, 1);
                s += __shfl_xor_sync(0xffffffffu, s, 2);
                q += __shfl_xor_sync(0xffffffffu, q, 1);
                q += __shfl_xor_sync(0xffffffffu, q, 2);
                if ((lane & 3) == 0){
                    psum[c - c0][wl] = s;
                    psq[c - c0][wl]  = q;
                }
            }
        }
        __syncthreads();
        const int bidx = b*8 + lt;
        if (tid < 128){
            float s = psum[tid][0] + psum[tid][1] + psum[tid][2] + psum[tid][3];
            g_psumT[bidx][c0 + tid] = s;
        } else if (tid < 256){
            const int cl = tid - 128;
            float q = psq[cl][0] + psq[cl][1] + psq[cl][2] + psq[cl][3];
            g_psqT[bidx][c0 + cl] = q;
        }
        __syncthreads();
    }

    // ---- fused BN final reduce: grid barrier, CTAs 0-7 do the work ----
    __threadfence();
    __syncthreads();
    if (tid == 0) atomicAdd(&g_arrive, 1u);
    if (blockIdx.x < 8){
        if (tid == 0){
            while (atomicAdd(&g_arrive, 0u) < (unsigned)CONV_GRID) {}
        }
        __syncthreads();
        __threadfence();
        const int cl = tid & 63;
        const int jg = tid >> 6;
        const int c = blockIdx.x*64 + cl;
        float s = 0.f, q = 0.f;
        #pragma unroll 8
        for (int j = jg*64; j < jg*64 + 64; j++){
            s += g_psumT[j][c];
            q += g_psqT[j][c];
        }
        ss[jg][cl] = s; qq[jg][cl] = q;
        __syncthreads();
        if (tid < 64){
            float st = ss[0][tid] + ss[1][tid] + ss[2][tid] + ss[3][tid];
            float qt = qq[0][tid] + qq[1][tid] + qq[2][tid] + qq[3][tid];
            float m = st*(1.0f/(BB*LL));
            float var = qt*(1.0f/(BB*LL)) - m*m;
            g_mean[blockIdx.x*64 + tid] = m;
            g_rstd[blockIdx.x*64 + tid] = rsqrtf(var + 1e-5f);
        }
        __syncthreads();
        if (tid == 0){
            unsigned int d = atomicAdd(&g_done, 1u);
            if (d == 7u){                      // 8th finisher resets for replay
                atomicExch(&g_arrive, 0u);
                atomicExch(&g_done, 0u);
            }
        }
    }
}

// ---------------------------------------------------------------------------
// K3: weight absmean partials
// ---------------------------------------------------------------------------
__global__ __launch_bounds__(256) void wabs_part_kernel(const float* __restrict__ pw){
    const int tid = threadIdx.x;
    const int base = blockIdx.x*4096;
    float s = 0.f;
    #pragma unroll
    for (int j = 0; j < 16; j++) s += fabsf(pw[base + tid + j*256]);
    __shared__ float sa[256];
    sa[tid] = s; __syncthreads();
    for (int off=128; off>0; off>>=1){
        if (tid<off) sa[tid]+=sa[tid+off];
        __syncthreads();
    }
    if (tid==0) g_wpart[blockIdx.x] = sa[0];
}

// ---------------------------------------------------------------------------
// K4: ternary quantize + pack; final wabs reduce fused.
// ---------------------------------------------------------------------------
__global__ __launch_bounds__(256) void wpack_kernel(const float* __restrict__ pw){
    __shared__ float sa[64];
    __shared__ float sc_sh;
    const int tid = threadIdx.x;
    if (tid < 64) sa[tid] = g_wpart[tid];
    __syncthreads();
    if (tid < 32){
        for (int off=32; off>0; off>>=1){
            if (tid < off && tid + off < 64) sa[tid]+=sa[tid+off];
            __syncwarp();
        }
        if (tid==0){
            float m = fmaxf(sa[0]*(1.0f/(CC*CC)), 1e-5f);
            sc_sh = 1.0f/m;
            if (blockIdx.x == 0){
                g_wrecip_d = m;
                g_wscale_d = 1.0f/m;
            }
        }
    }
    __syncthreads();
    const float sc = sc_sh;
    const int p = blockIdx.x*256 + tid;
    unsigned int packv = 0;
    #pragma unroll
    for (int j=0;j<4;j++){
        float t = rintf(pw[p*4+j]*sc);
        t = fmaxf(-1.f, fminf(1.f, t));
        int v = (int)t;
        packv |= ((unsigned int)(v & 0xFF)) << (8*j);
    }
    g_wq[p] = packv;
}

// ---------------------------------------------------------------------------
// K5: BN + GELU + per-token absmax + int8 pack. Single g_act read via smem.
// ---------------------------------------------------------------------------
#define TSROW 36
#define QUANT_SMEM ((512*TSROW + 512 + 512 + 32*33 + 32)*4)

__global__ __launch_bounds__(256) void quant_kernel(const float* __restrict__ gamma,
                                                    const float* __restrict__ beta){
    extern __shared__ float qs[];
    float* ts   = qs;                 // [512][TSROW]
    float* rowA = qs + 512*TSROW;     // 512
    float* rowB = rowA + 512;         // 512
    float* lmax = rowB + 512;         // [32][33]
    float* scal = lmax + 32*33;       // 32

    const int b  = blockIdx.y;
    const int l0 = blockIdx.x*32;
    const int tid = threadIdx.x;

    #pragma unroll
    for (int r = tid; r < 512; r += 256){
        float a = g_rstd[r]*gamma[r];
        rowA[r] = a;
        rowB[r] = beta[r] - g_mean[r]*a;
    }
    __syncthreads();

    const int rr = tid >> 3, ck = tid & 7;
    float lm0=0.f, lm1=0.f, lm2=0.f, lm3=0.f;
    #pragma unroll 4
    for (int j = 0; j < 16; j++){
        const int r = rr + 32*j;
        float4 v = *(const float4*)&g_act[((size_t)b*CC + r)*LL + l0 + ck*4];
        const float sa = rowA[r], sb = rowB[r];
        float4 y;
        y.x = gelu_f(sa*v.x + sb);
        y.y = gelu_f(sa*v.y + sb);
        y.z = gelu_f(sa*v.z + sb);
        y.w = gelu_f(sa*v.w + sb);
        *(float4*)&ts[r*TSROW + ck*4] = y;
        lm0 = fmaxf(lm0, fabsf(y.x));
        lm1 = fmaxf(lm1, fabsf(y.y));
        lm2 = fmaxf(lm2, fabsf(y.z));
        lm3 = fmaxf(lm3, fabsf(y.w));
    }
    lmax[rr*33 + ck*4+0] = lm0;
    lmax[rr*33 + ck*4+1] = lm1;
    lmax[rr*33 + ck*4+2] = lm2;
    lmax[rr*33 + ck*4+3] = lm3;
    __syncthreads();

    if (tid < 32){
        float m = 0.f;
        #pragma unroll
        for (int s = 0; s < 32; s++) m = fmaxf(m, lmax[s*33 + tid]);
        float am = fmaxf(m, 1e-5f);
        scal[tid] = 127.0f/am;
        g_arecip[b*LL + l0 + tid] = am*(1.0f/127.0f);
    }
    __syncthreads();

    const int lane = tid & 31, cs = tid >> 5;
    const float scl = scal[lane];
    #pragma unroll
    for (int cg = cs; cg < 128; cg += 8){
        unsigned int packv = 0;
        #pragma unroll
        for (int j = 0; j < 4; j++){
            float y = ts[(cg*4+j)*TSROW + lane];
            int v = (int)rintf(y*scl);
            v = max(-128, min(127, v));
            packv |= ((unsigned int)(v & 0xFF)) << (8*j);
        }
        g_xq[((size_t)b*LL + l0 + lane)*128 + cg] = packv;
    }
}

// ---------------------------------------------------------------------------
// K6: int8 ternary matmul via IMMA m16n8k32. One token tile per CTA (X loaded
// once); c0 loop inside re-loads only the 33KB W slice (L2-hot).
// ---------------------------------------------------------------------------
#define MM_ROWB 528
#define MMW_TILE (64*MM_ROWB)              // 33792 (W slice)
#define MM_SMEM (MMW_TILE + 128*MM_ROWB)   // 101376

__global__ __launch_bounds__(256) void matmul_imma_kernel(const float* __restrict__ xin,
                                                          float* __restrict__ out){
    extern __shared__ char msm[];
    const uint32_t sbase = smem_to_u32(msm);
    const int tid = threadIdx.x;
    const int lane = tid & 31, wid = tid >> 5;
    const int wc = wid & 1, wl = wid >> 1;

    const int tok0 = blockIdx.x*128;
    const int b  = tok0 >> 10;
    const int l0 = tok0 & (LL-1);

    for (int idx = tid; idx < 128*32; idx += 256){
        const int row = idx >> 5, chkk = idx & 31;
        CP_ASYNC16(sbase + MMW_TILE + row*MM_ROWB + chkk*16,
                   (const char*)g_xq + ((size_t)(tok0+row))*512 + chkk*16);
    }
    for (int idx = tid; idx < 64*32; idx += 256){
        const int row = idx >> 5, chkk = idx & 31;
        CP_ASYNC16(sbase + row*MM_ROWB + chkk*16,
                   (const char*)g_wq + ((size_t)row)*512 + chkk*16);
    }
    CP_COMMIT();

    const float wr = g_wrecip_d;
    const int lcol = wl*32 + (lane & 3)*2;
    float2 ar[4];
    #pragma unroll
    for (int nf = 0; nf < 4; nf++)
        ar[nf] = *(const float2*)&g_arecip[tok0 + lcol + nf*8];

    for (int c0i = 0; c0i < 8; c0i++){
        const int c0 = c0i*64;
        CP_WAIT0();
        __syncthreads();

        int acc[2][4][4];
        #pragma unroll
        for (int i=0;i<2;i++)
            #pragma unroll
            for (int j=0;j<4;j++)
                #pragma unroll
                for (int q=0;q<4;q++) acc[i][j][q]=0;

        #pragma unroll 4
        for (int k = 0; k < 16; k++){
            const uint32_t colb = (uint32_t)(k*32 + (lane >> 4)*16);
            uint32_t a[2][4];
            #pragma unroll
            for (int mf = 0; mf < 2; mf++){
                const uint32_t r = (uint32_t)(wc*32 + mf*16 + (lane & 15));
                LDSM4(a[mf][0],a[mf][1],a[mf][2],a[mf][3], sbase + r*MM_ROWB + colb);
            }
            uint32_t bt[4][2];
            #pragma unroll
            for (int g = 0; g < 2; g++){
                const uint32_t r = (uint32_t)(wl*32 + g*16 + (lane & 15));
                uint32_t t0,t1,t2,t3;
                LDSM4(t0,t1,t2,t3, sbase + MMW_TILE + r*MM_ROWB + colb);
                bt[g*2][0]=t0; bt[g*2+1][0]=t1; bt[g*2][1]=t2; bt[g*2+1][1]=t3;
            }
            #pragma unroll
            for (int mf = 0; mf < 2; mf++){
                #pragma unroll
                for (int nf = 0; nf < 4; nf++)
                    IMMA16832(acc[mf][nf], a[mf], bt[nf][0], bt[nf][1]);
            }
        }
        __syncthreads();
        if (c0i + 1 < 8){
            const int cn = (c0i+1)*64;
            for (int idx = tid; idx < 64*32; idx += 256){
                const int row = idx >> 5, chkk = idx & 31;
                CP_ASYNC16(sbase + row*MM_ROWB + chkk*16,
                           (const char*)g_wq + ((size_t)(cn+row))*512 + chkk*16);
            }
            CP_COMMIT();
        }

        #pragma unroll
        for (int mf = 0; mf < 2; mf++){
            const int rbase = c0 + wc*32 + mf*16 + (lane >> 2);
            #pragma unroll
            for (int half = 0; half < 2; half++){
                const int o = rbase + half*8;
                const float* rsrc = &xin[((size_t)b*CC + o)*LL + l0 + lcol];
                float* dst = &out[((size_t)b*CC + o)*LL + l0 + lcol];
                #pragma unroll
                for (int nf = 0; nf < 4; nf++){
                    const float2 rx = *(const float2*)(rsrc + nf*8);
                    float2 v;
                    v.x = gelu_f((float)acc[mf][nf][half*2+0]*ar[nf].x*wr) + rx.x;
                    v.y = gelu_f((float)acc[mf][nf][half*2+1]*ar[nf].y*wr) + rx.y;
                    *(float2*)(dst + nf*8) = v;
                }
            }
        }
    }
}

// ---------------------------------------------------------------------------
extern "C" void kernel_launch(void* const* d_in, const int* in_sizes, int n_in,
                              void* d_out, int out_size){
    const float* x      = (const float*)d_in[0];
    const float* conv_w = (const float*)d_in[1];
    const float* conv_b = (const float*)d_in[2];
    const float* gamma  = (const float*)d_in[3];
    const float* beta   = (const float*)d_in[4];
    const float* proj_w = (const float*)d_in[5];
    float* out = (float*)d_out;

    static bool init_done = false;
    static cudaStream_t sSide;
    static cudaEvent_t evFork, evW, evSide;
    if (!init_done){
        cudaFuncSetAttribute(conv_mma_kernel,
                             cudaFuncAttributeMaxDynamicSharedMemorySize, CONV_SMEM);
        cudaFuncSetAttribute(quant_kernel,
                             cudaFuncAttributeMaxDynamicSharedMemorySize, QUANT_SMEM);
        cudaFuncSetAttribute(matmul_imma_kernel,
                             cudaFuncAttributeMaxDynamicSharedMemorySize, MM_SMEM);
        cudaStreamCreateWithFlags(&sSide, cudaStreamNonBlocking);
        cudaEventCreateWithFlags(&evFork, cudaEventDisableTiming);
        cudaEventCreateWithFlags(&evW,    cudaEventDisableTiming);
        cudaEventCreateWithFlags(&evSide, cudaEventDisableTiming);
        init_done = true;
    }

    // fork: proj_w chain on side stream, x chain on main stream
    cudaEventRecord(evFork, 0);
    cudaStreamWaitEvent(sSide, evFork, 0);
    prep_w_kernel<<<512, 256, 0, sSide>>>(conv_w);
    cudaEventRecord(evW, sSide);
    wabs_part_kernel<<<64, 256, 0, sSide>>>(proj_w);
    wpack_kernel<<<256, 256, 0, sSide>>>(proj_w);
    cudaEventRecord(evSide, sSide);

    prep_x_kernel<<<dim3(32,16,32), 256>>>(x);
    cudaStreamWaitEvent(0, evW, 0);
    conv_mma_kernel<<<CONV_GRID, 256, CONV_SMEM>>>(conv_b);   // includes BN reduce
    quant_kernel<<<dim3(32,32), 256, QUANT_SMEM>>>(gamma, beta);
    cudaStreamWaitEvent(0, evSide, 0);
    matmul_imma_kernel<<<256, 256, MM_SMEM>>>(x, out);
}

// round 17
// speedup vs baseline: 1.2307x; 1.2307x over previous
#include <cuda_runtime.h>
#include <cuda_fp16.h>
#include <cstdint>

#define BB 32
#define CC 512
#define LL 1024
#define LPAD (LL + 2)

// ---------------------------------------------------------------------------
// Scratch (static device globals -- allocation-free per harness rules)
// ---------------------------------------------------------------------------
__device__ float g_act[BB*CC*LL];                   // conv output [B,C,L]
__device__ unsigned int g_xq[BB*LL*(CC/4)];         // packed int8 activations [B,L,C/4]
__device__ float g_arecip[BB*LL];                   // per-token absmax/127
__device__ float g_mean[CC];
__device__ float g_rstd[CC];
__device__ float g_wrecip_d;
__device__ float g_wscale_d;
__device__ float g_wpart[64];
__device__ unsigned int g_wq[CC*(CC/4)];            // packed ternary weights [O,C/4]
__device__ float g_psumT[256][CC];                  // [b*8+ltile][c] partial sums
__device__ float g_psqT[256][CC];

// fp16 operands for tensor-core conv
__device__ __half g_xhiT[BB*LPAD*CC];               // x transposed [b][l+1][i]
__device__ __half g_whi[3*CC*CC];                   // w [tap][c][i]

__device__ __forceinline__ float gelu_f(float v){
    return 0.5f*v*(1.0f + erff(v*0.70710678118654752440f));
}

__device__ __forceinline__ uint32_t smem_to_u32(const void* smem_ptr) {
    uint32_t addr;
    asm("{ .reg .u64 tmp; cvta.to.shared.u64 tmp, %1; cvt.u32.u64 %0, tmp; }"
        : "=r"(addr) : "l"(smem_ptr));
    return addr;
}

#define CP_ASYNC16(dst_u32, src_ptr) \
    asm volatile("cp.async.cg.shared.global [%0], [%1], 16;" \
        :: "r"(dst_u32), "l"(src_ptr))
#define CP_COMMIT() asm volatile("cp.async.commit_group;" ::: "memory")
#define CP_WAIT1()  asm volatile("cp.async.wait_group 1;" ::: "memory")
#define CP_WAIT0()  asm volatile("cp.async.wait_group 0;" ::: "memory")

#define LDSM4(r0,r1,r2,r3,addr) \
    asm volatile("ldmatrix.sync.aligned.m8n8.x4.shared.b16 {%0,%1,%2,%3}, [%4];" \
        : "=r"(r0),"=r"(r1),"=r"(r2),"=r"(r3) : "r"(addr))

#define MMA16816(c, a, b0, b1) \
    asm volatile("mma.sync.aligned.m16n8k16.row.col.f32.f16.f16.f32 " \
        "{%0,%1,%2,%3}, {%4,%5,%6,%7}, {%8,%9}, {%0,%1,%2,%3};" \
        : "+f"((c)[0]),"+f"((c)[1]),"+f"((c)[2]),"+f"((c)[3]) \
        : "r"((a)[0]),"r"((a)[1]),"r"((a)[2]),"r"((a)[3]), "r"(b0),"r"(b1))

#define IMMA16832(c, a, b0, b1) \
    asm volatile("mma.sync.aligned.m16n8k32.row.col.s32.s8.s8.s32 " \
        "{%0,%1,%2,%3}, {%4,%5,%6,%7}, {%8,%9}, {%0,%1,%2,%3};" \
        : "+r"((c)[0]),"+r"((c)[1]),"+r"((c)[2]),"+r"((c)[3]) \
        : "r"((a)[0]),"r"((a)[1]),"r"((a)[2]),"r"((a)[3]), "r"(b0),"r"(b1))

// ---------------------------------------------------------------------------
// P1: transpose + fp16 convert of x, half2 stores; halo rows fused in.
// ---------------------------------------------------------------------------
__global__ __launch_bounds__(256) void prep_x_kernel(const float* __restrict__ x){
    __shared__ float ts[32][33];
    const int b  = blockIdx.z;
    const int i0 = blockIdx.y*32;
    const int l0 = blockIdx.x*32;
    const int tx = threadIdx.x & 31, ty = threadIdx.x >> 5;

    if (blockIdx.x == 0 && threadIdx.x < 64){
        const int r = threadIdx.x >> 5;
        const int i = i0 + (threadIdx.x & 31);
        size_t o = ((size_t)b*LPAD + (r ? LPAD-1 : 0))*CC + i;
        g_xhiT[o] = __float2half(0.f);
    }

    #pragma unroll
    for (int ii = ty; ii < 32; ii += 8)
        ts[ii][tx] = x[((size_t)b*CC + i0 + ii)*LL + l0 + tx];
    __syncthreads();
    const int ip = threadIdx.x & 15;
    const int lr = threadIdx.x >> 4;
    #pragma unroll
    for (int pass = 0; pass < 2; pass++){
        const int ll = lr + pass*16;
        __half h0 = __float2half(ts[2*ip  ][ll]);
        __half h1 = __float2half(ts[2*ip+1][ll]);
        size_t o = ((size_t)b*LPAD + l0 + ll + 1)*CC + i0 + 2*ip;
        *(__half2*)&g_xhiT[o] = __halves2half2(h0, h1);
    }
}

// P2: conv_w [c][i][3] -> g_whi [tap][c][i] fp16, half2 writes
__global__ __launch_bounds__(256) void prep_w_kernel(const float* __restrict__ w){
    int idx = blockIdx.x*256 + threadIdx.x;      // 131072
    int c = idx >> 8, jp = idx & 255;
    int i0 = jp*2;
    const float* src = w + ((size_t)c*CC + i0)*3;
    #pragma unroll
    for (int k = 0; k < 3; k++){
        __half h0 = __float2half(src[k]);
        __half h1 = __float2half(src[3+k]);
        *(__half2*)&g_whi[((size_t)k*CC + c)*CC + i0] = __halves2half2(h0, h1);
    }
}

// ---------------------------------------------------------------------------
// K1: Persistent Conv1d fp16 HMMA (whi*xhi only), kc-outer/taps-inner,
//     2-stage cp.async, fused BN partials (quad shuffle pre-reduce).
// ---------------------------------------------------------------------------
#define WTILE_B 10240               // 128 rows * 80B
#define XTILE_B 10400               // 130 rows * 80B
#define STAGE_B (3*WTILE_B + XTILE_B)     // 41120
#define CONV_SMEM (2*STAGE_B)             // 82240
#define CONV_GRID 296
#define N_TILES 1024

__global__ __launch_bounds__(256, 2) void conv_mma_kernel(const float* __restrict__ bias){
    extern __shared__ char smem[];
    __shared__ float psum[128][4];
    __shared__ float psq[128][4];
    const uint32_t sbase = smem_to_u32(smem);
    const int tid = threadIdx.x;
    const int lane = tid & 31, wid = tid >> 5;
    const int wc = wid & 1, wl = wid >> 1;

    for (int tile = blockIdx.x; tile < N_TILES; tile += CONV_GRID){
        const int b  = tile >> 5;
        const int c0 = ((tile >> 3) & 3) << 7;
        const int lt = tile & 7;
        const int l0 = lt << 7;

        float acc[4][4][4];
        #pragma unroll
        for (int i=0;i<4;i++)
            #pragma unroll
            for (int j=0;j<4;j++)
                #pragma unroll
                for (int q=0;q<4;q++) acc[i][j][q]=0.f;

        #define ISSUE(kc, stg) do { \
            const uint32_t st_ = sbase + (stg)*STAGE_B; \
            const int koff_ = (kc)*32; \
            for (int idx = tid; idx < 1536; idx += 256){ \
                const int tap_ = idx >> 9, r_ = (idx >> 2) & 127, ch_ = idx & 3; \
                CP_ASYNC16(st_ + tap_*WTILE_B + r_*80 + ch_*16, \
                           g_whi + ((size_t)(tap_*CC + c0 + r_))*CC + koff_ + ch_*8); \
            } \
            for (int idx = tid; idx < 520; idx += 256){ \
                const int r_ = idx >> 2, ch_ = idx & 3; \
                CP_ASYNC16(st_ + 3*WTILE_B + r_*80 + ch_*16, \
                           g_xhiT + ((size_t)b*LPAD + l0 + r_)*CC + koff_ + ch_*8); \
            } \
        } while(0)

        ISSUE(0, 0);
        CP_COMMIT();
        ISSUE(1, 1);
        CP_COMMIT();

        for (int kc = 0; kc < 16; kc++){
            if (kc + 1 < 16) CP_WAIT1(); else CP_WAIT0();
            __syncthreads();

            const uint32_t st = sbase + (kc & 1)*STAGE_B;
            const uint32_t xb = st + 3*WTILE_B;
            #pragma unroll
            for (int kh = 0; kh < 2; kh++){
                const uint32_t colb = (uint32_t)(kh*32 + (lane >> 4)*16);
                #pragma unroll
                for (int tap = 0; tap < 3; tap++){
                    uint32_t a[4][4];
                    #pragma unroll
                    for (int mf = 0; mf < 4; mf++){
                        const uint32_t r = (uint32_t)(wc*64 + mf*16 + (lane & 15));
                        LDSM4(a[mf][0],a[mf][1],a[mf][2],a[mf][3],
                              st + tap*WTILE_B + r*80 + colb);
                    }
                    uint32_t bhi[4][2];
                    #pragma unroll
                    for (int g = 0; g < 2; g++){
                        const uint32_t r = (uint32_t)(tap + wl*32 + g*16 + (lane & 15));
                        uint32_t t0,t1,t2,t3;
                        LDSM4(t0,t1,t2,t3, xb + r*80 + colb);
                        bhi[g*2][0]=t0; bhi[g*2+1][0]=t1; bhi[g*2][1]=t2; bhi[g*2+1][1]=t3;
                    }
                    #pragma unroll
                    for (int mf = 0; mf < 4; mf++){
                        #pragma unroll
                        for (int nf = 0; nf < 4; nf++)
                            MMA16816(acc[mf][nf], a[mf], bhi[nf][0], bhi[nf][1]);
                    }
                }
            }
            __syncthreads();
            if (kc + 2 < 16){
                ISSUE(kc+2, kc & 1);
                CP_COMMIT();
            }
        }
        #undef ISSUE

        // ---- epilogue: bias + store + BN partials ----
        const int lcol = l0 + wl*32 + (lane & 3)*2;
        #pragma unroll
        for (int mf = 0; mf < 4; mf++){
            const int rbase = c0 + wc*64 + mf*16 + (lane >> 2);
            #pragma unroll
            for (int half = 0; half < 2; half++){
                const int c = rbase + half*8;
                const float bv = bias[c];
                float* dst = &g_act[((size_t)b*CC + c)*LL + lcol];
                float s = 0.f, q = 0.f;
                #pragma unroll
                for (int nf = 0; nf < 4; nf++){
                    float2 v;
                    v.x = acc[mf][nf][half*2+0] + bv;
                    v.y = acc[mf][nf][half*2+1] + bv;
                    *(float2*)(dst + nf*8) = v;
                    s += v.x + v.y;
                    q += v.x*v.x + v.y*v.y;
                }
                s += __shfl_xor_sync(0xffffffffu, s, 1);
                s += __shfl_xor_sync(0xffffffffu, s, 2);
                q += __shfl_xor_sync(0xffffffffu, q, 1);
                q += __shfl_xor_sync(0xffffffffu, q, 2);
                if ((lane & 3) == 0){
                    psum[c - c0][wl] = s;
                    psq[c - c0][wl]  = q;
                }
            }
        }
        __syncthreads();
        const int bidx = b*8 + lt;
        if (tid < 128){
            float s = psum[tid][0] + psum[tid][1] + psum[tid][2] + psum[tid][3];
            g_psumT[bidx][c0 + tid] = s;
        } else if (tid < 256){
            const int cl = tid - 128;
            float q = psq[cl][0] + psq[cl][1] + psq[cl][2] + psq[cl][3];
            g_psqT[bidx][c0 + cl] = q;
        }
        __syncthreads();
    }
}

// ---------------------------------------------------------------------------
// K2: BN final reduce -- grid 8, per-channel 4-way j split (fixed order)
// ---------------------------------------------------------------------------
__global__ __launch_bounds__(256) void bnred_kernel(){
    __shared__ float ss[4][64], qq[4][64];
    const int tid = threadIdx.x;
    const int cl = tid & 63;
    const int jg = tid >> 6;
    const int c = blockIdx.x*64 + cl;
    float s = 0.f, q = 0.f;
    #pragma unroll 8
    for (int j = jg*64; j < jg*64 + 64; j++){
        s += g_psumT[j][c];
        q += g_psqT[j][c];
    }
    ss[jg][cl] = s; qq[jg][cl] = q;
    __syncthreads();
    if (tid < 64){
        float st = ss[0][tid] + ss[1][tid] + ss[2][tid] + ss[3][tid];
        float qt = qq[0][tid] + qq[1][tid] + qq[2][tid] + qq[3][tid];
        float m = st*(1.0f/(BB*LL));
        float var = qt*(1.0f/(BB*LL)) - m*m;
        g_mean[blockIdx.x*64 + tid] = m;
        g_rstd[blockIdx.x*64 + tid] = rsqrtf(var + 1e-5f);
    }
}

// ---------------------------------------------------------------------------
// K3: weight absmean partials
// ---------------------------------------------------------------------------
__global__ __launch_bounds__(256) void wabs_part_kernel(const float* __restrict__ pw){
    const int tid = threadIdx.x;
    const int base = blockIdx.x*4096;
    float s = 0.f;
    #pragma unroll
    for (int j = 0; j < 16; j++) s += fabsf(pw[base + tid + j*256]);
    __shared__ float sa[256];
    sa[tid] = s; __syncthreads();
    for (int off=128; off>0; off>>=1){
        if (tid<off) sa[tid]+=sa[tid+off];
        __syncthreads();
    }
    if (tid==0) g_wpart[blockIdx.x] = sa[0];
}

// ---------------------------------------------------------------------------
// K4: ternary quantize + pack; final wabs reduce fused.
// ---------------------------------------------------------------------------
__global__ __launch_bounds__(256) void wpack_kernel(const float* __restrict__ pw){
    __shared__ float sa[64];
    __shared__ float sc_sh;
    const int tid = threadIdx.x;
    if (tid < 64) sa[tid] = g_wpart[tid];
    __syncthreads();
    if (tid < 32){
        for (int off=32; off>0; off>>=1){
            if (tid < off && tid + off < 64) sa[tid]+=sa[tid+off];
            __syncwarp();
        }
        if (tid==0){
            float m = fmaxf(sa[0]*(1.0f/(CC*CC)), 1e-5f);
            sc_sh = 1.0f/m;
            if (blockIdx.x == 0){
                g_wrecip_d = m;
                g_wscale_d = 1.0f/m;
            }
        }
    }
    __syncthreads();
    const float sc = sc_sh;
    const int p = blockIdx.x*256 + tid;
    unsigned int packv = 0;
    #pragma unroll
    for (int j=0;j<4;j++){
        float t = rintf(pw[p*4+j]*sc);
        t = fmaxf(-1.f, fminf(1.f, t));
        int v = (int)t;
        packv |= ((unsigned int)(v & 0xFF)) << (8*j);
    }
    g_wq[p] = packv;
}

// ---------------------------------------------------------------------------
// K5: BN + GELU + per-token absmax + int8 pack. Single g_act read via smem.
// ---------------------------------------------------------------------------
#define TSROW 36
#define QUANT_SMEM ((512*TSROW + 512 + 512 + 32*33 + 32)*4)

__global__ __launch_bounds__(256) void quant_kernel(const float* __restrict__ gamma,
                                                    const float* __restrict__ beta){
    extern __shared__ float qs[];
    float* ts   = qs;                 // [512][TSROW]
    float* rowA = qs + 512*TSROW;     // 512
    float* rowB = rowA + 512;         // 512
    float* lmax = rowB + 512;         // [32][33]
    float* scal = lmax + 32*33;       // 32

    const int b  = blockIdx.y;
    const int l0 = blockIdx.x*32;
    const int tid = threadIdx.x;

    #pragma unroll
    for (int r = tid; r < 512; r += 256){
        float a = g_rstd[r]*gamma[r];
        rowA[r] = a;
        rowB[r] = beta[r] - g_mean[r]*a;
    }
    __syncthreads();

    const int rr = tid >> 3, ck = tid & 7;
    float lm0=0.f, lm1=0.f, lm2=0.f, lm3=0.f;
    #pragma unroll 4
    for (int j = 0; j < 16; j++){
        const int r = rr + 32*j;
        float4 v = *(const float4*)&g_act[((size_t)b*CC + r)*LL + l0 + ck*4];
        const float sa = rowA[r], sb = rowB[r];
        float4 y;
        y.x = gelu_f(sa*v.x + sb);
        y.y = gelu_f(sa*v.y + sb);
        y.z = gelu_f(sa*v.z + sb);
        y.w = gelu_f(sa*v.w + sb);
        *(float4*)&ts[r*TSROW + ck*4] = y;
        lm0 = fmaxf(lm0, fabsf(y.x));
        lm1 = fmaxf(lm1, fabsf(y.y));
        lm2 = fmaxf(lm2, fabsf(y.z));
        lm3 = fmaxf(lm3, fabsf(y.w));
    }
    lmax[rr*33 + ck*4+0] = lm0;
    lmax[rr*33 + ck*4+1] = lm1;
    lmax[rr*33 + ck*4+2] = lm2;
    lmax[rr*33 + ck*4+3] = lm3;
    __syncthreads();

    if (tid < 32){
        float m = 0.f;
        #pragma unroll
        for (int s = 0; s < 32; s++) m = fmaxf(m, lmax[s*33 + tid]);
        float am = fmaxf(m, 1e-5f);
        scal[tid] = 127.0f/am;
        g_arecip[b*LL + l0 + tid] = am*(1.0f/127.0f);
    }
    __syncthreads();

    const int lane = tid & 31, cs = tid >> 5;
    const float scl = scal[lane];
    #pragma unroll
    for (int cg = cs; cg < 128; cg += 8){
        unsigned int packv = 0;
        #pragma unroll
        for (int j = 0; j < 4; j++){
            float y = ts[(cg*4+j)*TSROW + lane];
            int v = (int)rintf(y*scl);
            v = max(-128, min(127, v));
            packv |= ((unsigned int)(v & 0xFF)) << (8*j);
        }
        g_xq[((size_t)b*LL + l0 + lane)*128 + cg] = packv;
    }
}

// ---------------------------------------------------------------------------
// K6: int8 ternary matmul via IMMA m16n8k32. One token tile per CTA (X loaded
// once); c0 loop inside re-loads only the 33KB W slice (L2-hot).
// ---------------------------------------------------------------------------
#define MM_ROWB 528
#define MMW_TILE (64*MM_ROWB)              // 33792 (W slice)
#define MM_SMEM (MMW_TILE + 128*MM_ROWB)   // 101376

__global__ __launch_bounds__(256) void matmul_imma_kernel(const float* __restrict__ xin,
                                                          float* __restrict__ out){
    extern __shared__ char msm[];
    const uint32_t sbase = smem_to_u32(msm);
    const int tid = threadIdx.x;
    const int lane = tid & 31, wid = tid >> 5;
    const int wc = wid & 1, wl = wid >> 1;

    const int tok0 = blockIdx.x*128;
    const int b  = tok0 >> 10;
    const int l0 = tok0 & (LL-1);

    for (int idx = tid; idx < 128*32; idx += 256){
        const int row = idx >> 5, chkk = idx & 31;
        CP_ASYNC16(sbase + MMW_TILE + row*MM_ROWB + chkk*16,
                   (const char*)g_xq + ((size_t)(tok0+row))*512 + chkk*16);
    }
    for (int idx = tid; idx < 64*32; idx += 256){
        const int row = idx >> 5, chkk = idx & 31;
        CP_ASYNC16(sbase + row*MM_ROWB + chkk*16,
                   (const char*)g_wq + ((size_t)row)*512 + chkk*16);
    }
    CP_COMMIT();

    const float wr = g_wrecip_d;
    const int lcol = wl*32 + (lane & 3)*2;
    float2 ar[4];
    #pragma unroll
    for (int nf = 0; nf < 4; nf++)
        ar[nf] = *(const float2*)&g_arecip[tok0 + lcol + nf*8];

    for (int c0i = 0; c0i < 8; c0i++){
        const int c0 = c0i*64;
        CP_WAIT0();
        __syncthreads();

        int acc[2][4][4];
        #pragma unroll
        for (int i=0;i<2;i++)
            #pragma unroll
            for (int j=0;j<4;j++)
                #pragma unroll
                for (int q=0;q<4;q++) acc[i][j][q]=0;

        #pragma unroll 4
        for (int k = 0; k < 16; k++){
            const uint32_t colb = (uint32_t)(k*32 + (lane >> 4)*16);
            uint32_t a[2][4];
            #pragma unroll
            for (int mf = 0; mf < 2; mf++){
                const uint32_t r = (uint32_t)(wc*32 + mf*16 + (lane & 15));
                LDSM4(a[mf][0],a[mf][1],a[mf][2],a[mf][3], sbase + r*MM_ROWB + colb);
            }
            uint32_t bt[4][2];
            #pragma unroll
            for (int g = 0; g < 2; g++){
                const uint32_t r = (uint32_t)(wl*32 + g*16 + (lane & 15));
                uint32_t t0,t1,t2,t3;
                LDSM4(t0,t1,t2,t3, sbase + MMW_TILE + r*MM_ROWB + colb);
                bt[g*2][0]=t0; bt[g*2+1][0]=t1; bt[g*2][1]=t2; bt[g*2+1][1]=t3;
            }
            #pragma unroll
            for (int mf = 0; mf < 2; mf++){
                #pragma unroll
                for (int nf = 0; nf < 4; nf++)
                    IMMA16832(acc[mf][nf], a[mf], bt[nf][0], bt[nf][1]);
            }
        }
        __syncthreads();
        if (c0i + 1 < 8){
            const int cn = (c0i+1)*64;
            for (int idx = tid; idx < 64*32; idx += 256){
                const int row = idx >> 5, chkk = idx & 31;
                CP_ASYNC16(sbase + row*MM_ROWB + chkk*16,
                           (const char*)g_wq + ((size_t)(cn+row))*512 + chkk*16);
            }
            CP_COMMIT();
        }

        #pragma unroll
        for (int mf = 0; mf < 2; mf++){
            const int rbase = c0 + wc*32 + mf*16 + (lane >> 2);
            #pragma unroll
            for (int half = 0; half < 2; half++){
                const int o = rbase + half*8;
                const float* rsrc = &xin[((size_t)b*CC + o)*LL + l0 + lcol];
                float* dst = &out[((size_t)b*CC + o)*LL + l0 + lcol];
                #pragma unroll
                for (int nf = 0; nf < 4; nf++){
                    const float2 rx = *(const float2*)(rsrc + nf*8);
                    float2 v;
                    v.x = gelu_f((float)acc[mf][nf][half*2+0]*ar[nf].x*wr) + rx.x;
                    v.y = gelu_f((float)acc[mf][nf][half*2+1]*ar[nf].y*wr) + rx.y;
                    *(float2*)(dst + nf*8) = v;
                }
            }
        }
    }
}

// ---------------------------------------------------------------------------
extern "C" void kernel_launch(void* const* d_in, const int* in_sizes, int n_in,
                              void* d_out, int out_size){
    const float* x      = (const float*)d_in[0];
    const float* conv_w = (const float*)d_in[1];
    const float* conv_b = (const float*)d_in[2];
    const float* gamma  = (const float*)d_in[3];
    const float* beta   = (const float*)d_in[4];
    const float* proj_w = (const float*)d_in[5];
    float* out = (float*)d_out;

    static bool init_done = false;
    static cudaStream_t sSide;
    static cudaEvent_t evFork, evW, evSide;
    if (!init_done){
        cudaFuncSetAttribute(conv_mma_kernel,
                             cudaFuncAttributeMaxDynamicSharedMemorySize, CONV_SMEM);
        cudaFuncSetAttribute(quant_kernel,
                             cudaFuncAttributeMaxDynamicSharedMemorySize, QUANT_SMEM);
        cudaFuncSetAttribute(matmul_imma_kernel,
                             cudaFuncAttributeMaxDynamicSharedMemorySize, MM_SMEM);
        cudaStreamCreateWithFlags(&sSide, cudaStreamNonBlocking);
        cudaEventCreateWithFlags(&evFork, cudaEventDisableTiming);
        cudaEventCreateWithFlags(&evW,    cudaEventDisableTiming);
        cudaEventCreateWithFlags(&evSide, cudaEventDisableTiming);
        init_done = true;
    }

    // fork: proj_w chain on side stream, x chain on main stream
    cudaEventRecord(evFork, 0);
    cudaStreamWaitEvent(sSide, evFork, 0);
    prep_w_kernel<<<512, 256, 0, sSide>>>(conv_w);
    cudaEventRecord(evW, sSide);
    wabs_part_kernel<<<64, 256, 0, sSide>>>(proj_w);
    wpack_kernel<<<256, 256, 0, sSide>>>(proj_w);
    cudaEventRecord(evSide, sSide);

    prep_x_kernel<<<dim3(32,16,32), 256>>>(x);
    cudaStreamWaitEvent(0, evW, 0);
    conv_mma_kernel<<<CONV_GRID, 256, CONV_SMEM>>>(conv_b);
    bnred_kernel<<<8, 256>>>();
    quant_kernel<<<dim3(32,32), 256, QUANT_SMEM>>>(gamma, beta);
    cudaStreamWaitEvent(0, evSide, 0);
    matmul_imma_kernel<<<256, 256, MM_SMEM>>>(x, out);
}